// round 2
// baseline (speedup 1.0000x reference)
#include <cuda_runtime.h>

// ---------------- static scratch (no allocation allowed) ----------------
#define N_MAX 100000

__device__ __align__(256) float d_deg[N_MAX];
__device__ __align__(256) float d_dinv[N_MAX];
__device__ __align__(256) float d_h1[N_MAX * 64];   // holds h1 * dinv (prescaled)
__device__ __align__(256) float d_g1[N_MAX * 64];   // agg accumulator, then relu input
__device__ __align__(256) float d_z[N_MAX * 2];     // (relu(g1)@W2f) * dinv
__device__ __align__(256) float d_logits[N_MAX * 2];
__device__ float d_W2f[64 * 2];   // W2 @ Wl1 @ Wl2
__device__ float d_bc[2];         // folded bias
__device__ unsigned d_cmax[2];
__device__ float d_csum[2];

// ---------------- helpers ----------------
__device__ __forceinline__ unsigned encf(float f) {
    unsigned u = __float_as_uint(f);
    return (u & 0x80000000u) ? ~u : (u | 0x80000000u);
}
__device__ __forceinline__ float decf(unsigned u) {
    return (u & 0x80000000u) ? __uint_as_float(u ^ 0x80000000u)
                             : __uint_as_float(~u);
}

// ---------------- kernels ----------------

// deg = 1 (self loop), zero reduction cells + logits accumulator
__global__ void k_init(int n) {
    int i = blockIdx.x * blockDim.x + threadIdx.x;
    if (i < n) {
        d_deg[i] = 1.0f;
        d_logits[2 * i]     = 0.0f;
        d_logits[2 * i + 1] = 0.0f;
    }
    if (i < 2) { d_cmax[i] = 0u; d_csum[i] = 0.0f; }
}

__global__ void k_deg(const int* __restrict__ dst, int E) {
    int e = blockIdx.x * blockDim.x + threadIdx.x;
    if (e < E) atomicAdd(&d_deg[dst[e]], 1.0f);
}

__global__ void k_dinv(int n) {
    int i = blockIdx.x * blockDim.x + threadIdx.x;
    if (i < n) d_dinv[i] = rsqrtf(d_deg[i]);
}

// zero the 64-wide aggregation accumulator
__global__ void k_zero_g1(int n16) {
    int idx = blockIdx.x * blockDim.x + threadIdx.x;
    if (idx < n16) ((float4*)d_g1)[idx] = make_float4(0.f, 0.f, 0.f, 0.f);
}

// h1p = (x @ W1) * dinv[row].  BM=64, 256 threads, 4x4 register tile.
__global__ void k_gemm1(const float* __restrict__ x, const float* __restrict__ W, int n) {
    __shared__ float xs[64][33];
    __shared__ float ws[32][64];
    int t  = threadIdx.x;
    int ty = t >> 4, tx = t & 15;
    int m0 = blockIdx.x * 64;
    float acc[4][4] = {};

    for (int kc = 0; kc < 128; kc += 32) {
        #pragma unroll
        for (int q = 0; q < 2; q++) {                 // x tile: 64x32
            int id = t + q * 256;
            int r = id >> 3;
            int c = (id & 7) * 4;
            int node = m0 + r;
            float4 v = make_float4(0.f, 0.f, 0.f, 0.f);
            if (node < n) v = *(const float4*)&x[node * 128 + kc + c];
            xs[r][c + 0] = v.x; xs[r][c + 1] = v.y;
            xs[r][c + 2] = v.z; xs[r][c + 3] = v.w;
        }
        #pragma unroll
        for (int q = 0; q < 2; q++) {                 // W tile: 32x64
            int id = t + q * 256;
            int r = id >> 4;
            int c = (id & 15) * 4;
            *(float4*)&ws[r][c] = *(const float4*)&W[(kc + r) * 64 + c];
        }
        __syncthreads();
        #pragma unroll
        for (int k = 0; k < 32; k++) {
            float4 b = *(float4*)&ws[k][tx * 4];
            float a0 = xs[ty * 4 + 0][k];
            float a1 = xs[ty * 4 + 1][k];
            float a2 = xs[ty * 4 + 2][k];
            float a3 = xs[ty * 4 + 3][k];
            acc[0][0] += a0 * b.x; acc[0][1] += a0 * b.y; acc[0][2] += a0 * b.z; acc[0][3] += a0 * b.w;
            acc[1][0] += a1 * b.x; acc[1][1] += a1 * b.y; acc[1][2] += a1 * b.z; acc[1][3] += a1 * b.w;
            acc[2][0] += a2 * b.x; acc[2][1] += a2 * b.y; acc[2][2] += a2 * b.z; acc[2][3] += a2 * b.w;
            acc[3][0] += a3 * b.x; acc[3][1] += a3 * b.y; acc[3][2] += a3 * b.z; acc[3][3] += a3 * b.w;
        }
        __syncthreads();
    }
    #pragma unroll
    for (int i2 = 0; i2 < 4; i2++) {
        int node = m0 + ty * 4 + i2;
        if (node < n) {
            float s = d_dinv[node];   // prescale: h1p = h1 * dinv
            *(float4*)&d_h1[node * 64 + tx * 4] =
                make_float4(acc[i2][0] * s, acc[i2][1] * s, acc[i2][2] * s, acc[i2][3] * s);
        }
    }
}

// fold W2 @ Wl1 @ Wl2 -> d_W2f[64][2]; folded bias -> d_bc
__global__ void k_fold(const float* __restrict__ W2, const float* __restrict__ Wl1,
                       const float* __restrict__ Wl2, const float* __restrict__ b2,
                       const float* __restrict__ bl1, const float* __restrict__ bl2) {
    __shared__ float A[64][2];      // Wl1 @ Wl2
    int i = threadIdx.x;            // 64 threads
    float a0 = 0.f, a1 = 0.f;
    for (int m = 0; m < 32; m++) {
        float w = Wl1[i * 32 + m];
        a0 += w * Wl2[m * 2 + 0];
        a1 += w * Wl2[m * 2 + 1];
    }
    A[i][0] = a0; A[i][1] = a1;
    __syncthreads();
    float f0 = 0.f, f1 = 0.f;
    for (int j = 0; j < 64; j++) {
        float w = W2[i * 64 + j];
        f0 += w * A[j][0];
        f1 += w * A[j][1];
    }
    d_W2f[i * 2 + 0] = f0;
    d_W2f[i * 2 + 1] = f1;
    if (i < 2) {
        float b = bl2[i];
        for (int j = 0; j < 64; j++) b += b2[j] * A[j][i];
        for (int m = 0; m < 32; m++) b += bl1[m] * Wl2[m * 2 + i];
        d_bc[i] = b;
    }
}

// Agg #1: 16 lanes per edge, float4 gather + red.v4 scatter-add of prescaled rows.
// Index loads are same-address within the 16-lane group -> broadcast, 1 sector.
__global__ void k_agg1(const int* __restrict__ src, const int* __restrict__ dst, int E) {
    int idx = blockIdx.x * blockDim.x + threadIdx.x;
    int e   = idx >> 4;
    if (e >= E) return;
    int sub = threadIdx.x & 15;
    int si = __ldg(&src[e]);
    int di = __ldg(&dst[e]);
    float4 h = *(const float4*)&d_h1[si * 64 + sub * 4];
    float* gp = &d_g1[di * 64 + sub * 4];
    asm volatile("red.global.add.v4.f32 [%0], {%1,%2,%3,%4};"
                 :: "l"(gp), "f"(h.x), "f"(h.y), "f"(h.z), "f"(h.w) : "memory");
}

// post: g1 = dinv[i]*(agg + self) + b1   (self term = h1p[i], already *dinv once)
__global__ void k_g1post(const float* __restrict__ b1, int n16) {
    int idx = blockIdx.x * blockDim.x + threadIdx.x;
    if (idx >= n16) return;
    int i = idx >> 4, q = idx & 15;
    float s = d_dinv[i];
    float4 g = ((float4*)d_g1)[idx];
    float4 h = ((const float4*)d_h1)[idx];
    float4 bv = *(const float4*)&b1[q * 4];
    ((float4*)d_g1)[idx] = make_float4(s * (g.x + h.x) + bv.x,
                                       s * (g.y + h.y) + bv.y,
                                       s * (g.z + h.z) + bv.z,
                                       s * (g.w + h.w) + bv.w);
}

// zp = (relu(g1) @ W2f) * dinv   (2 floats per node)
__global__ void k_z(int n) {
    __shared__ float wf[128];
    if (threadIdx.x < 128) wf[threadIdx.x] = d_W2f[threadIdx.x];
    __syncthreads();
    int i = blockIdx.x * blockDim.x + threadIdx.x;
    if (i >= n) return;
    const float4* g = (const float4*)&d_g1[i * 64];
    float z0 = 0.f, z1 = 0.f;
    #pragma unroll
    for (int q = 0; q < 16; q++) {
        float4 v = g[q];
        float v0 = fmaxf(v.x, 0.f), v1 = fmaxf(v.y, 0.f);
        float v2 = fmaxf(v.z, 0.f), v3 = fmaxf(v.w, 0.f);
        int b = q * 8;
        z0 += v0 * wf[b + 0]; z1 += v0 * wf[b + 1];
        z0 += v1 * wf[b + 2]; z1 += v1 * wf[b + 3];
        z0 += v2 * wf[b + 4]; z1 += v2 * wf[b + 5];
        z0 += v3 * wf[b + 6]; z1 += v3 * wf[b + 7];
    }
    float s = d_dinv[i];
    ((float2*)d_z)[i] = make_float2(z0 * s, z1 * s);
}

// Agg #2: one thread per edge, red.v2 of 2-float messages.
__global__ void k_agg2(const int* __restrict__ src, const int* __restrict__ dst, int E) {
    int e = blockIdx.x * blockDim.x + threadIdx.x;
    if (e >= E) return;
    int si = src[e], di = dst[e];
    float2 z = ((const float2*)d_z)[si];
    float* lp = &d_logits[di * 2];
    asm volatile("red.global.add.v2.f32 [%0], {%1,%2};"
                 :: "l"(lp), "f"(z.x), "f"(z.y) : "memory");
}

// post: logits = dinv*(agg + self) + bc
__global__ void k_lpost(int n) {
    int i = blockIdx.x * blockDim.x + threadIdx.x;
    if (i >= n) return;
    float s  = d_dinv[i];
    float2 l = ((float2*)d_logits)[i];
    float2 z = ((const float2*)d_z)[i];
    ((float2*)d_logits)[i] = make_float2(s * (l.x + z.x) + d_bc[0],
                                         s * (l.y + z.y) + d_bc[1]);
}

__global__ void k_max(int n) {
    float m0 = -1e30f, m1 = -1e30f;
    for (int i = blockIdx.x * blockDim.x + threadIdx.x; i < n; i += gridDim.x * blockDim.x) {
        float2 l = ((const float2*)d_logits)[i];
        m0 = fmaxf(m0, l.x); m1 = fmaxf(m1, l.y);
    }
    #pragma unroll
    for (int o = 16; o; o >>= 1) {
        m0 = fmaxf(m0, __shfl_xor_sync(0xffffffffu, m0, o));
        m1 = fmaxf(m1, __shfl_xor_sync(0xffffffffu, m1, o));
    }
    if ((threadIdx.x & 31) == 0) {
        atomicMax(&d_cmax[0], encf(m0));
        atomicMax(&d_cmax[1], encf(m1));
    }
}

__global__ void k_sum(int n) {
    float m0 = decf(d_cmax[0]), m1 = decf(d_cmax[1]);
    float s0 = 0.f, s1 = 0.f;
    for (int i = blockIdx.x * blockDim.x + threadIdx.x; i < n; i += gridDim.x * blockDim.x) {
        float2 l = ((const float2*)d_logits)[i];
        s0 += expf(l.x - m0);
        s1 += expf(l.y - m1);
    }
    #pragma unroll
    for (int o = 16; o; o >>= 1) {
        s0 += __shfl_xor_sync(0xffffffffu, s0, o);
        s1 += __shfl_xor_sync(0xffffffffu, s1, o);
    }
    if ((threadIdx.x & 31) == 0) {
        atomicAdd(&d_csum[0], s0);
        atomicAdd(&d_csum[1], s1);
    }
}

__global__ void k_out(float* __restrict__ out, int n) {
    int i = blockIdx.x * blockDim.x + threadIdx.x;
    if (i >= n) return;
    float m0 = decf(d_cmax[0]), m1 = decf(d_cmax[1]);
    float r0 = 1.0f / d_csum[0], r1 = 1.0f / d_csum[1];
    float2 l = ((const float2*)d_logits)[i];
    out[2 * i + 0] = expf(l.x - m0) * r0;
    out[2 * i + 1] = expf(l.y - m1) * r1;
}

// ---------------- launch ----------------
extern "C" void kernel_launch(void* const* d_in, const int* in_sizes, int n_in,
                              void* d_out, int out_size) {
    const float* x   = (const float*)d_in[0];
    const int*   ei  = (const int*)d_in[1];     // int32! (JAX x64 disabled)
    const float* W1  = (const float*)d_in[2];
    const float* b1  = (const float*)d_in[3];
    const float* W2  = (const float*)d_in[4];
    const float* b2  = (const float*)d_in[5];
    const float* Wl1 = (const float*)d_in[6];
    const float* bl1 = (const float*)d_in[7];
    const float* Wl2 = (const float*)d_in[8];
    const float* bl2 = (const float*)d_in[9];
    float* out = (float*)d_out;

    int n = in_sizes[0] / 128;
    int E = in_sizes[1] / 2;
    const int* src = ei;
    const int* dst = ei + E;
    int n16 = n * 16;

    k_init   <<<(n + 255) / 256, 256>>>(n);
    k_deg    <<<(E + 255) / 256, 256>>>(dst, E);
    k_dinv   <<<(n + 255) / 256, 256>>>(n);
    k_zero_g1<<<(n16 + 255) / 256, 256>>>(n16);
    k_gemm1  <<<(n + 63) / 64, 256>>>(x, W1, n);
    k_fold   <<<1, 64>>>(W2, Wl1, Wl2, b2, bl1, bl2);

    long long w1 = (long long)E * 16;
    k_agg1   <<<(int)((w1 + 255) / 256), 256>>>(src, dst, E);
    k_g1post <<<(n16 + 255) / 256, 256>>>(b1, n16);
    k_z      <<<(n + 255) / 256, 256>>>(n);
    k_agg2   <<<(E + 255) / 256, 256>>>(src, dst, E);
    k_lpost  <<<(n + 255) / 256, 256>>>(n);
    k_max    <<<512, 256>>>(n);
    k_sum    <<<512, 256>>>(n);
    k_out    <<<(n + 255) / 256, 256>>>(out, n);
}

// round 3
// speedup vs baseline: 1.4347x; 1.4347x over previous
#include <cuda_runtime.h>

// ---------------- static scratch (no allocation allowed) ----------------
#define N_MAX 100032
#define E_MAX 3400000

__device__ __align__(256) float d_h1[100000 * 64];   // h1 * dinv (prescaled)
__device__ __align__(256) float d_z[100000 * 2];     // (relu(g1)@W2f) * dinv
__device__ __align__(256) float d_logits[100000 * 2];
__device__ __align__(256) int   d_cnt[N_MAX];        // in-degree histogram (excl self)
__device__ __align__(256) int   d_roff[N_MAX + 1];   // CSR row offsets
__device__ __align__(256) int   d_cursor[N_MAX];     // scatter cursors
__device__ __align__(256) int   d_ssrc[E_MAX];       // src sorted by dst
__device__ __align__(256) int   d_blk[256];          // scan block sums
__device__ float d_W2f[64 * 2];                      // W2 @ Wl1 @ Wl2
__device__ float d_bc[2];                            // folded bias
__device__ unsigned d_cmax[2];
__device__ float d_csum[2];

// ---------------- helpers ----------------
__device__ __forceinline__ unsigned encf(float f) {
    unsigned u = __float_as_uint(f);
    return (u & 0x80000000u) ? ~u : (u | 0x80000000u);
}
__device__ __forceinline__ float decf(unsigned u) {
    return (u & 0x80000000u) ? __uint_as_float(u ^ 0x80000000u)
                             : __uint_as_float(~u);
}

// ---------------- CSR build ----------------
__global__ void k_init0(int n) {
    int i = blockIdx.x * blockDim.x + threadIdx.x;
    if (i < n) d_cnt[i] = 0;
    if (i < 2) { d_cmax[i] = 0u; d_csum[i] = 0.0f; }
}

__global__ void k_hist(const int* __restrict__ dst, int E) {
    int e = blockIdx.x * blockDim.x + threadIdx.x;
    if (e < E) atomicAdd(&d_cnt[dst[e]], 1);
}

// scanA: per-1024-element block sums
__global__ void k_scanA(int n) {
    __shared__ int sh[256];
    int t = threadIdx.x, b = blockIdx.x;
    int base = b * 1024 + t * 4;
    int s = 0;
    #pragma unroll
    for (int j = 0; j < 4; j++) { int i = base + j; if (i < n) s += d_cnt[i]; }
    sh[t] = s; __syncthreads();
    #pragma unroll
    for (int o = 128; o; o >>= 1) {
        if (t < o) sh[t] += sh[t + o];
        __syncthreads();
    }
    if (t == 0) d_blk[b] = sh[0];
}

// scanB: single-block exclusive scan of block sums (nb <= 256)
__global__ void k_scanB(int nb) {
    __shared__ int sh[256];
    int t = threadIdx.x;
    int v = (t < nb) ? d_blk[t] : 0;
    sh[t] = v; __syncthreads();
    for (int o = 1; o < 256; o <<= 1) {
        int tv = (t >= o) ? sh[t - o] : 0;
        __syncthreads();
        sh[t] += tv;
        __syncthreads();
    }
    if (t < nb) d_blk[t] = sh[t] - v;   // exclusive
}

// scanC: final offsets + cursor copy
__global__ void k_scanC(int n) {
    __shared__ int sh[256];
    int t = threadIdx.x, b = blockIdx.x;
    int base = b * 1024 + t * 4;
    int v[4];
    #pragma unroll
    for (int j = 0; j < 4; j++) { int i = base + j; v[j] = (i < n) ? d_cnt[i] : 0; }
    int tsum = v[0] + v[1] + v[2] + v[3];
    sh[t] = tsum; __syncthreads();
    for (int o = 1; o < 256; o <<= 1) {
        int tv = (t >= o) ? sh[t - o] : 0;
        __syncthreads();
        sh[t] += tv;
        __syncthreads();
    }
    int run = sh[t] - tsum + d_blk[b];
    #pragma unroll
    for (int j = 0; j < 4; j++) {
        int i = base + j;
        if (i < n) { d_roff[i] = run; d_cursor[i] = run; }
        run += v[j];
        if (i == n - 1) d_roff[n] = run;
    }
}

__global__ void k_scatter(const int* __restrict__ src, const int* __restrict__ dst, int E) {
    int e = blockIdx.x * blockDim.x + threadIdx.x;
    if (e >= E) return;
    int p = atomicAdd(&d_cursor[dst[e]], 1);
    d_ssrc[p] = src[e];
}

// ---------------- dense math ----------------

// h1p = (x @ W1) * dinv[row].  BM=64, 256 threads, 4x4 register tile.
__global__ void k_gemm1(const float* __restrict__ x, const float* __restrict__ W, int n) {
    __shared__ float xs[64][33];
    __shared__ float ws[32][64];
    int t  = threadIdx.x;
    int ty = t >> 4, tx = t & 15;
    int m0 = blockIdx.x * 64;
    float acc[4][4] = {};

    for (int kc = 0; kc < 128; kc += 32) {
        #pragma unroll
        for (int q = 0; q < 2; q++) {                 // x tile: 64x32
            int id = t + q * 256;
            int r = id >> 3;
            int c = (id & 7) * 4;
            int node = m0 + r;
            float4 v = make_float4(0.f, 0.f, 0.f, 0.f);
            if (node < n) v = *(const float4*)&x[node * 128 + kc + c];
            xs[r][c + 0] = v.x; xs[r][c + 1] = v.y;
            xs[r][c + 2] = v.z; xs[r][c + 3] = v.w;
        }
        #pragma unroll
        for (int q = 0; q < 2; q++) {                 // W tile: 32x64
            int id = t + q * 256;
            int r = id >> 4;
            int c = (id & 15) * 4;
            *(float4*)&ws[r][c] = *(const float4*)&W[(kc + r) * 64 + c];
        }
        __syncthreads();
        #pragma unroll
        for (int k = 0; k < 32; k++) {
            float4 b = *(float4*)&ws[k][tx * 4];
            float a0 = xs[ty * 4 + 0][k];
            float a1 = xs[ty * 4 + 1][k];
            float a2 = xs[ty * 4 + 2][k];
            float a3 = xs[ty * 4 + 3][k];
            acc[0][0] += a0 * b.x; acc[0][1] += a0 * b.y; acc[0][2] += a0 * b.z; acc[0][3] += a0 * b.w;
            acc[1][0] += a1 * b.x; acc[1][1] += a1 * b.y; acc[1][2] += a1 * b.z; acc[1][3] += a1 * b.w;
            acc[2][0] += a2 * b.x; acc[2][1] += a2 * b.y; acc[2][2] += a2 * b.z; acc[2][3] += a2 * b.w;
            acc[3][0] += a3 * b.x; acc[3][1] += a3 * b.y; acc[3][2] += a3 * b.z; acc[3][3] += a3 * b.w;
        }
        __syncthreads();
    }
    #pragma unroll
    for (int i2 = 0; i2 < 4; i2++) {
        int node = m0 + ty * 4 + i2;
        if (node < n) {
            float s = rsqrtf((float)d_cnt[node] + 1.0f);   // dinv prescale
            *(float4*)&d_h1[node * 64 + tx * 4] =
                make_float4(acc[i2][0] * s, acc[i2][1] * s, acc[i2][2] * s, acc[i2][3] * s);
        }
    }
}

// fold W2 @ Wl1 @ Wl2 -> d_W2f[64][2]; folded bias -> d_bc
__global__ void k_fold(const float* __restrict__ W2, const float* __restrict__ Wl1,
                       const float* __restrict__ Wl2, const float* __restrict__ b2,
                       const float* __restrict__ bl1, const float* __restrict__ bl2) {
    __shared__ float A[64][2];      // Wl1 @ Wl2
    int i = threadIdx.x;            // 64 threads
    float a0 = 0.f, a1 = 0.f;
    for (int m = 0; m < 32; m++) {
        float w = Wl1[i * 32 + m];
        a0 += w * Wl2[m * 2 + 0];
        a1 += w * Wl2[m * 2 + 1];
    }
    A[i][0] = a0; A[i][1] = a1;
    __syncthreads();
    float f0 = 0.f, f1 = 0.f;
    for (int j = 0; j < 64; j++) {
        float w = W2[i * 64 + j];
        f0 += w * A[j][0];
        f1 += w * A[j][1];
    }
    d_W2f[i * 2 + 0] = f0;
    d_W2f[i * 2 + 1] = f1;
    if (i < 2) {
        float b = bl2[i];
        for (int j = 0; j < 64; j++) b += b2[j] * A[j][i];
        for (int m = 0; m < 32; m++) b += bl1[m] * Wl2[m * 2 + i];
        d_bc[i] = b;
    }
}

// ---------------- fused pull-aggregation #1 ----------------
// warp per node: acc64 in regs (float2/lane) <- sum h1p[src];
// then g = dinv*(acc+self)+b1, relu, project to 2 via W2f, *dinv -> d_z.
__global__ void k_agg1z(const float* __restrict__ b1, int n) {
    __shared__ float wf[128];
    if (threadIdx.x < 128) wf[threadIdx.x] = d_W2f[threadIdx.x];
    __syncthreads();

    int w = (blockIdx.x * blockDim.x + threadIdx.x) >> 5;
    if (w >= n) return;
    int lane = threadIdx.x & 31;
    int c = lane * 2;

    int start = d_roff[w];
    int cnt   = d_roff[w + 1] - start;

    float ax = 0.f, ay = 0.f;
    const int* sp = &d_ssrc[start];
    int j = 0;
    for (; j + 4 <= cnt; j += 4) {
        int s0 = __ldg(&sp[j + 0]);
        int s1 = __ldg(&sp[j + 1]);
        int s2 = __ldg(&sp[j + 2]);
        int s3 = __ldg(&sp[j + 3]);
        float2 a0 = *(const float2*)&d_h1[s0 * 64 + c];
        float2 a1 = *(const float2*)&d_h1[s1 * 64 + c];
        float2 a2 = *(const float2*)&d_h1[s2 * 64 + c];
        float2 a3 = *(const float2*)&d_h1[s3 * 64 + c];
        ax += (a0.x + a1.x) + (a2.x + a3.x);
        ay += (a0.y + a1.y) + (a2.y + a3.y);
    }
    for (; j < cnt; j++) {
        int s0 = __ldg(&sp[j]);
        float2 a0 = *(const float2*)&d_h1[s0 * 64 + c];
        ax += a0.x; ay += a0.y;
    }

    float s = rsqrtf((float)cnt + 1.0f);
    float2 self = *(const float2*)&d_h1[w * 64 + c];
    float2 bv   = *(const float2*)&b1[c];
    float gx = fmaxf(s * (ax + self.x) + bv.x, 0.f);
    float gy = fmaxf(s * (ay + self.y) + bv.y, 0.f);

    float z0 = gx * wf[2 * c + 0] + gy * wf[2 * c + 2];
    float z1 = gx * wf[2 * c + 1] + gy * wf[2 * c + 3];
    #pragma unroll
    for (int o = 16; o; o >>= 1) {
        z0 += __shfl_xor_sync(0xffffffffu, z0, o);
        z1 += __shfl_xor_sync(0xffffffffu, z1, o);
    }
    if (lane == 0)
        ((float2*)d_z)[w] = make_float2(z0 * s, z1 * s);
}

// ---------------- fused pull-aggregation #2 + logits epilogue ----------------
__global__ void k_agg2l(int n) {
    int w = (blockIdx.x * blockDim.x + threadIdx.x) >> 5;
    if (w >= n) return;
    int lane = threadIdx.x & 31;

    int start = d_roff[w];
    int cnt   = d_roff[w + 1] - start;

    float z0 = 0.f, z1 = 0.f;
    for (int j = lane; j < cnt; j += 32) {
        int si = __ldg(&d_ssrc[start + j]);
        float2 zz = ((const float2*)d_z)[si];
        z0 += zz.x; z1 += zz.y;
    }
    #pragma unroll
    for (int o = 16; o; o >>= 1) {
        z0 += __shfl_xor_sync(0xffffffffu, z0, o);
        z1 += __shfl_xor_sync(0xffffffffu, z1, o);
    }
    if (lane == 0) {
        float s = rsqrtf((float)cnt + 1.0f);
        float2 self = ((const float2*)d_z)[w];
        ((float2*)d_logits)[w] = make_float2(s * (z0 + self.x) + d_bc[0],
                                             s * (z1 + self.y) + d_bc[1]);
    }
}

// ---------------- softmax over nodes ----------------
__global__ void k_max(int n) {
    float m0 = -1e30f, m1 = -1e30f;
    for (int i = blockIdx.x * blockDim.x + threadIdx.x; i < n; i += gridDim.x * blockDim.x) {
        float2 l = ((const float2*)d_logits)[i];
        m0 = fmaxf(m0, l.x); m1 = fmaxf(m1, l.y);
    }
    #pragma unroll
    for (int o = 16; o; o >>= 1) {
        m0 = fmaxf(m0, __shfl_xor_sync(0xffffffffu, m0, o));
        m1 = fmaxf(m1, __shfl_xor_sync(0xffffffffu, m1, o));
    }
    if ((threadIdx.x & 31) == 0) {
        atomicMax(&d_cmax[0], encf(m0));
        atomicMax(&d_cmax[1], encf(m1));
    }
}

__global__ void k_sum(int n) {
    float m0 = decf(d_cmax[0]), m1 = decf(d_cmax[1]);
    float s0 = 0.f, s1 = 0.f;
    for (int i = blockIdx.x * blockDim.x + threadIdx.x; i < n; i += gridDim.x * blockDim.x) {
        float2 l = ((const float2*)d_logits)[i];
        s0 += expf(l.x - m0);
        s1 += expf(l.y - m1);
    }
    #pragma unroll
    for (int o = 16; o; o >>= 1) {
        s0 += __shfl_xor_sync(0xffffffffu, s0, o);
        s1 += __shfl_xor_sync(0xffffffffu, s1, o);
    }
    if ((threadIdx.x & 31) == 0) {
        atomicAdd(&d_csum[0], s0);
        atomicAdd(&d_csum[1], s1);
    }
}

__global__ void k_out(float* __restrict__ out, int n) {
    int i = blockIdx.x * blockDim.x + threadIdx.x;
    if (i >= n) return;
    float m0 = decf(d_cmax[0]), m1 = decf(d_cmax[1]);
    float r0 = 1.0f / d_csum[0], r1 = 1.0f / d_csum[1];
    float2 l = ((const float2*)d_logits)[i];
    out[2 * i + 0] = expf(l.x - m0) * r0;
    out[2 * i + 1] = expf(l.y - m1) * r1;
}

// ---------------- launch ----------------
extern "C" void kernel_launch(void* const* d_in, const int* in_sizes, int n_in,
                              void* d_out, int out_size) {
    const float* x   = (const float*)d_in[0];
    const int*   ei  = (const int*)d_in[1];     // int32 (JAX x64 disabled)
    const float* W1  = (const float*)d_in[2];
    const float* b1  = (const float*)d_in[3];
    const float* W2  = (const float*)d_in[4];
    const float* b2  = (const float*)d_in[5];
    const float* Wl1 = (const float*)d_in[6];
    const float* bl1 = (const float*)d_in[7];
    const float* Wl2 = (const float*)d_in[8];
    const float* bl2 = (const float*)d_in[9];
    float* out = (float*)d_out;

    int n = in_sizes[0] / 128;
    int E = in_sizes[1] / 2;
    const int* src = ei;
    const int* dst = ei + E;
    int nb = (n + 1023) / 1024;

    k_init0  <<<(n + 255) / 256, 256>>>(n);
    k_hist   <<<(E + 255) / 256, 256>>>(dst, E);
    k_gemm1  <<<(n + 63) / 64, 256>>>(x, W1, n);
    k_scanA  <<<nb, 256>>>(n);
    k_scanB  <<<1, 256>>>(nb);
    k_scanC  <<<nb, 256>>>(n);
    k_scatter<<<(E + 255) / 256, 256>>>(src, dst, E);
    k_fold   <<<1, 64>>>(W2, Wl1, Wl2, b2, bl1, bl2);

    k_agg1z  <<<(n * 32 + 255) / 256, 256>>>(b1, n);
    k_agg2l  <<<(n * 32 + 255) / 256, 256>>>(n);
    k_max    <<<256, 256>>>(n);
    k_sum    <<<256, 256>>>(n);
    k_out    <<<(n + 255) / 256, 256>>>(out, n);
}

// round 4
// speedup vs baseline: 1.4468x; 1.0084x over previous
#include <cuda_runtime.h>
#include <cuda_fp16.h>

// ---------------- static scratch (no allocation allowed) ----------------
#define N_MAX 100032
#define E_MAX 3400000

__device__ __align__(256) __half d_h1h[100000 * 64]; // h1 * dinv, fp16
__device__ __align__(256) float d_z[100000 * 2];     // (relu(g1)@W2f) * dinv
__device__ __align__(256) float d_logits[100000 * 2];
__device__ __align__(256) int   d_cnt[N_MAX];        // in-degree histogram (excl self)
__device__ __align__(256) int   d_roff[N_MAX + 1];   // CSR row offsets
__device__ __align__(256) int   d_cursor[N_MAX];     // scatter cursors
__device__ __align__(256) int   d_ssrc[E_MAX];       // src sorted by dst
__device__ __align__(256) int   d_blk[256];          // scan block sums
__device__ float d_W2f[64 * 2];                      // W2 @ Wl1 @ Wl2
__device__ float d_bc[2];                            // folded bias
__device__ unsigned d_cmax[2];
__device__ float d_csum[2];

// ---------------- helpers ----------------
__device__ __forceinline__ unsigned encf(float f) {
    unsigned u = __float_as_uint(f);
    return (u & 0x80000000u) ? ~u : (u | 0x80000000u);
}
__device__ __forceinline__ float decf(unsigned u) {
    return (u & 0x80000000u) ? __uint_as_float(u ^ 0x80000000u)
                             : __uint_as_float(~u);
}
// packed f32x2 (sm_103a FMA pipe does 2 fp32 lanes per FFMA slot)
__device__ __forceinline__ void fma2(unsigned long long& d, unsigned long long a, unsigned long long b) {
    asm("fma.rn.f32x2 %0, %1, %2, %0;" : "+l"(d) : "l"(a), "l"(b));
}
__device__ __forceinline__ unsigned long long pk2(float lo, float hi) {
    unsigned long long r;
    asm("mov.b64 %0, {%1, %2};" : "=l"(r) : "f"(lo), "f"(hi));
    return r;
}
__device__ __forceinline__ float2 upk2(unsigned long long v) {
    float2 f;
    asm("mov.b64 {%0, %1}, %2;" : "=f"(f.x), "=f"(f.y) : "l"(v));
    return f;
}

// ---------------- CSR build ----------------
__global__ void k_init0(int n) {
    int i = blockIdx.x * blockDim.x + threadIdx.x;
    if (i < n) d_cnt[i] = 0;
    if (i < 2) { d_cmax[i] = 0u; d_csum[i] = 0.0f; }
}

__global__ void k_hist(const int* __restrict__ dst, int E) {
    int e = blockIdx.x * blockDim.x + threadIdx.x;
    if (e < E) atomicAdd(&d_cnt[dst[e]], 1);
}

// scanA: per-1024-element block sums
__global__ void k_scanA(int n) {
    __shared__ int sh[256];
    int t = threadIdx.x, b = blockIdx.x;
    int base = b * 1024 + t * 4;
    int s = 0;
    #pragma unroll
    for (int j = 0; j < 4; j++) { int i = base + j; if (i < n) s += d_cnt[i]; }
    sh[t] = s; __syncthreads();
    #pragma unroll
    for (int o = 128; o; o >>= 1) {
        if (t < o) sh[t] += sh[t + o];
        __syncthreads();
    }
    if (t == 0) d_blk[b] = sh[0];
}

// scanB: single-block exclusive scan of block sums (nb <= 256)
__global__ void k_scanB(int nb) {
    __shared__ int sh[256];
    int t = threadIdx.x;
    int v = (t < nb) ? d_blk[t] : 0;
    sh[t] = v; __syncthreads();
    for (int o = 1; o < 256; o <<= 1) {
        int tv = (t >= o) ? sh[t - o] : 0;
        __syncthreads();
        sh[t] += tv;
        __syncthreads();
    }
    if (t < nb) d_blk[t] = sh[t] - v;   // exclusive
}

// scanC: final offsets + cursor copy
__global__ void k_scanC(int n) {
    __shared__ int sh[256];
    int t = threadIdx.x, b = blockIdx.x;
    int base = b * 1024 + t * 4;
    int v[4];
    #pragma unroll
    for (int j = 0; j < 4; j++) { int i = base + j; v[j] = (i < n) ? d_cnt[i] : 0; }
    int tsum = v[0] + v[1] + v[2] + v[3];
    sh[t] = tsum; __syncthreads();
    for (int o = 1; o < 256; o <<= 1) {
        int tv = (t >= o) ? sh[t - o] : 0;
        __syncthreads();
        sh[t] += tv;
        __syncthreads();
    }
    int run = sh[t] - tsum + d_blk[b];
    #pragma unroll
    for (int j = 0; j < 4; j++) {
        int i = base + j;
        if (i < n) { d_roff[i] = run; d_cursor[i] = run; }
        run += v[j];
        if (i == n - 1) d_roff[n] = run;
    }
}

__global__ void k_scatter(const int* __restrict__ src, const int* __restrict__ dst, int E) {
    int e = blockIdx.x * blockDim.x + threadIdx.x;
    if (e >= E) return;
    int p = atomicAdd(&d_cursor[dst[e]], 1);
    d_ssrc[p] = src[e];
}

// ---------------- dense math ----------------

// h1p = (x @ W1) * dinv[row] -> fp16.  BM=64, 256 threads, 4x4 register tile,
// inner product via packed fma.rn.f32x2 (2x fp32 throughput on sm_103a).
__global__ void k_gemm1(const float* __restrict__ x, const float* __restrict__ W, int n) {
    __shared__ float xs[64][33];
    __shared__ float ws[32][64];
    int t  = threadIdx.x;
    int ty = t >> 4, tx = t & 15;
    int m0 = blockIdx.x * 64;
    unsigned long long acc[4][2] = {};   // 4 rows x 2 packed f32x2 (4 cols)

    for (int kc = 0; kc < 128; kc += 32) {
        #pragma unroll
        for (int q = 0; q < 2; q++) {                 // x tile: 64x32
            int id = t + q * 256;
            int r = id >> 3;
            int c = (id & 7) * 4;
            int node = m0 + r;
            float4 v = make_float4(0.f, 0.f, 0.f, 0.f);
            if (node < n) v = *(const float4*)&x[node * 128 + kc + c];
            xs[r][c + 0] = v.x; xs[r][c + 1] = v.y;
            xs[r][c + 2] = v.z; xs[r][c + 3] = v.w;
        }
        #pragma unroll
        for (int q = 0; q < 2; q++) {                 // W tile: 32x64
            int id = t + q * 256;
            int r = id >> 4;
            int c = (id & 15) * 4;
            *(float4*)&ws[r][c] = *(const float4*)&W[(kc + r) * 64 + c];
        }
        __syncthreads();
        #pragma unroll
        for (int k = 0; k < 32; k++) {
            float4 b = *(float4*)&ws[k][tx * 4];
            unsigned long long b01 = pk2(b.x, b.y);
            unsigned long long b23 = pk2(b.z, b.w);
            #pragma unroll
            for (int i2 = 0; i2 < 4; i2++) {
                float a = xs[ty * 4 + i2][k];
                unsigned long long aa = pk2(a, a);
                fma2(acc[i2][0], aa, b01);
                fma2(acc[i2][1], aa, b23);
            }
        }
        __syncthreads();
    }
    #pragma unroll
    for (int i2 = 0; i2 < 4; i2++) {
        int node = m0 + ty * 4 + i2;
        if (node < n) {
            float s = rsqrtf((float)d_cnt[node] + 1.0f);   // dinv prescale
            float2 p0 = upk2(acc[i2][0]);
            float2 p1 = upk2(acc[i2][1]);
            __half2 h0 = __floats2half2_rn(p0.x * s, p0.y * s);
            __half2 h1 = __floats2half2_rn(p1.x * s, p1.y * s);
            __half2* op = (__half2*)&d_h1h[node * 64 + tx * 4];
            op[0] = h0; op[1] = h1;
        }
    }
}

// fold W2 @ Wl1 @ Wl2 -> d_W2f[64][2]; folded bias -> d_bc
__global__ void k_fold(const float* __restrict__ W2, const float* __restrict__ Wl1,
                       const float* __restrict__ Wl2, const float* __restrict__ b2,
                       const float* __restrict__ bl1, const float* __restrict__ bl2) {
    __shared__ float A[64][2];      // Wl1 @ Wl2
    int i = threadIdx.x;            // 64 threads
    float a0 = 0.f, a1 = 0.f;
    for (int m = 0; m < 32; m++) {
        float w = Wl1[i * 32 + m];
        a0 += w * Wl2[m * 2 + 0];
        a1 += w * Wl2[m * 2 + 1];
    }
    A[i][0] = a0; A[i][1] = a1;
    __syncthreads();
    float f0 = 0.f, f1 = 0.f;
    for (int j = 0; j < 64; j++) {
        float w = W2[i * 64 + j];
        f0 += w * A[j][0];
        f1 += w * A[j][1];
    }
    d_W2f[i * 2 + 0] = f0;
    d_W2f[i * 2 + 1] = f1;
    if (i < 2) {
        float b = bl2[i];
        for (int j = 0; j < 64; j++) b += b2[j] * A[j][i];
        for (int m = 0; m < 32; m++) b += bl1[m] * Wl2[m * 2 + i];
        d_bc[i] = b;
    }
}

// ---------------- fused pull-aggregation #1 ----------------
// warp per node: acc64 in regs (half2 gather -> fp32 acc) <- sum h1p[src];
// then g = dinv*(acc+self)+b1, relu, project to 2 via W2f, *dinv -> d_z.
__global__ void k_agg1z(const float* __restrict__ b1, int n) {
    __shared__ float wf[128];
    if (threadIdx.x < 128) wf[threadIdx.x] = d_W2f[threadIdx.x];
    __syncthreads();

    int w = (blockIdx.x * blockDim.x + threadIdx.x) >> 5;
    if (w >= n) return;
    int lane = threadIdx.x & 31;
    int c = lane * 2;

    int start = d_roff[w];
    int cnt   = d_roff[w + 1] - start;

    const __half2* hp = (const __half2*)d_h1h;
    float ax = 0.f, ay = 0.f;
    const int* sp = &d_ssrc[start];
    int j = 0;
    for (; j + 4 <= cnt; j += 4) {
        int s0 = __ldg(&sp[j + 0]);
        int s1 = __ldg(&sp[j + 1]);
        int s2 = __ldg(&sp[j + 2]);
        int s3 = __ldg(&sp[j + 3]);
        float2 a0 = __half22float2(hp[s0 * 32 + lane]);
        float2 a1 = __half22float2(hp[s1 * 32 + lane]);
        float2 a2 = __half22float2(hp[s2 * 32 + lane]);
        float2 a3 = __half22float2(hp[s3 * 32 + lane]);
        ax += (a0.x + a1.x) + (a2.x + a3.x);
        ay += (a0.y + a1.y) + (a2.y + a3.y);
    }
    for (; j < cnt; j++) {
        int s0 = __ldg(&sp[j]);
        float2 a0 = __half22float2(hp[s0 * 32 + lane]);
        ax += a0.x; ay += a0.y;
    }

    float s = rsqrtf((float)cnt + 1.0f);
    float2 self = __half22float2(hp[w * 32 + lane]);
    float2 bv   = *(const float2*)&b1[c];
    float gx = fmaxf(s * (ax + self.x) + bv.x, 0.f);
    float gy = fmaxf(s * (ay + self.y) + bv.y, 0.f);

    float z0 = gx * wf[2 * c + 0] + gy * wf[2 * c + 2];
    float z1 = gx * wf[2 * c + 1] + gy * wf[2 * c + 3];
    #pragma unroll
    for (int o = 16; o; o >>= 1) {
        z0 += __shfl_xor_sync(0xffffffffu, z0, o);
        z1 += __shfl_xor_sync(0xffffffffu, z1, o);
    }
    if (lane == 0)
        ((float2*)d_z)[w] = make_float2(z0 * s, z1 * s);
}

// ---------------- fused pull-aggregation #2 + logits epilogue ----------------
__global__ void k_agg2l(int n) {
    int w = (blockIdx.x * blockDim.x + threadIdx.x) >> 5;
    if (w >= n) return;
    int lane = threadIdx.x & 31;

    int start = d_roff[w];
    int cnt   = d_roff[w + 1] - start;

    float z0 = 0.f, z1 = 0.f;
    for (int j = lane; j < cnt; j += 32) {
        int si = __ldg(&d_ssrc[start + j]);
        float2 zz = ((const float2*)d_z)[si];
        z0 += zz.x; z1 += zz.y;
    }
    #pragma unroll
    for (int o = 16; o; o >>= 1) {
        z0 += __shfl_xor_sync(0xffffffffu, z0, o);
        z1 += __shfl_xor_sync(0xffffffffu, z1, o);
    }
    if (lane == 0) {
        float s = rsqrtf((float)cnt + 1.0f);
        float2 self = ((const float2*)d_z)[w];
        ((float2*)d_logits)[w] = make_float2(s * (z0 + self.x) + d_bc[0],
                                             s * (z1 + self.y) + d_bc[1]);
    }
}

// ---------------- softmax over nodes ----------------
__global__ void k_max(int n) {
    float m0 = -1e30f, m1 = -1e30f;
    for (int i = blockIdx.x * blockDim.x + threadIdx.x; i < n; i += gridDim.x * blockDim.x) {
        float2 l = ((const float2*)d_logits)[i];
        m0 = fmaxf(m0, l.x); m1 = fmaxf(m1, l.y);
    }
    #pragma unroll
    for (int o = 16; o; o >>= 1) {
        m0 = fmaxf(m0, __shfl_xor_sync(0xffffffffu, m0, o));
        m1 = fmaxf(m1, __shfl_xor_sync(0xffffffffu, m1, o));
    }
    if ((threadIdx.x & 31) == 0) {
        atomicMax(&d_cmax[0], encf(m0));
        atomicMax(&d_cmax[1], encf(m1));
    }
}

__global__ void k_sum(int n) {
    float m0 = decf(d_cmax[0]), m1 = decf(d_cmax[1]);
    float s0 = 0.f, s1 = 0.f;
    for (int i = blockIdx.x * blockDim.x + threadIdx.x; i < n; i += gridDim.x * blockDim.x) {
        float2 l = ((const float2*)d_logits)[i];
        s0 += expf(l.x - m0);
        s1 += expf(l.y - m1);
    }
    #pragma unroll
    for (int o = 16; o; o >>= 1) {
        s0 += __shfl_xor_sync(0xffffffffu, s0, o);
        s1 += __shfl_xor_sync(0xffffffffu, s1, o);
    }
    if ((threadIdx.x & 31) == 0) {
        atomicAdd(&d_csum[0], s0);
        atomicAdd(&d_csum[1], s1);
    }
}

__global__ void k_out(float* __restrict__ out, int n) {
    int i = blockIdx.x * blockDim.x + threadIdx.x;
    if (i >= n) return;
    float m0 = decf(d_cmax[0]), m1 = decf(d_cmax[1]);
    float r0 = 1.0f / d_csum[0], r1 = 1.0f / d_csum[1];
    float2 l = ((const float2*)d_logits)[i];
    out[2 * i + 0] = expf(l.x - m0) * r0;
    out[2 * i + 1] = expf(l.y - m1) * r1;
}

// ---------------- launch ----------------
extern "C" void kernel_launch(void* const* d_in, const int* in_sizes, int n_in,
                              void* d_out, int out_size) {
    const float* x   = (const float*)d_in[0];
    const int*   ei  = (const int*)d_in[1];     // int32 (JAX x64 disabled)
    const float* W1  = (const float*)d_in[2];
    const float* b1  = (const float*)d_in[3];
    const float* W2  = (const float*)d_in[4];
    const float* b2  = (const float*)d_in[5];
    const float* Wl1 = (const float*)d_in[6];
    const float* bl1 = (const float*)d_in[7];
    const float* Wl2 = (const float*)d_in[8];
    const float* bl2 = (const float*)d_in[9];
    float* out = (float*)d_out;

    int n = in_sizes[0] / 128;
    int E = in_sizes[1] / 2;
    const int* src = ei;
    const int* dst = ei + E;
    int nb = (n + 1023) / 1024;

    k_init0  <<<(n + 255) / 256, 256>>>(n);
    k_hist   <<<(E + 255) / 256, 256>>>(dst, E);
    k_gemm1  <<<(n + 63) / 64, 256>>>(x, W1, n);
    k_scanA  <<<nb, 256>>>(n);
    k_scanB  <<<1, 256>>>(nb);
    k_scanC  <<<nb, 256>>>(n);
    k_scatter<<<(E + 255) / 256, 256>>>(src, dst, E);
    k_fold   <<<1, 64>>>(W2, Wl1, Wl2, b2, bl1, bl2);

    k_agg1z  <<<(n * 32 + 255) / 256, 256>>>(b1, n);
    k_agg2l  <<<(n * 32 + 255) / 256, 256>>>(n);
    k_max    <<<256, 256>>>(n);
    k_sum    <<<256, 256>>>(n);
    k_out    <<<(n + 255) / 256, 256>>>(out, n);
}